// round 4
// baseline (speedup 1.0000x reference)
#include <cuda_runtime.h>
#include <cuda_bf16.h>

#define BT   32
#define NPTS 128
#define DIM  64
#define AH   256   // ATTN_HID
#define PH   64    // POS_HID
#define PIN  34

// ---------------- device scratch (no allocs allowed) ----------------
__device__ float g_A [BT*NPTS*DIM];   // p @ pm_w1.T  (no bias)
__device__ float g_U [BT*NPTS*AH];    // q @ am_w1.T
__device__ float g_WK[BT*NPTS*AH];    // k @ am_w1.T
__device__ float g_V [BT*NPTS*DIM];   // v
__device__ float g_WcT  [PH*AH];      // [h][m] : Wc[m][h] = sum_d am_w1[m][d]*pm_w2[d][h]
__device__ float g_AMW2T[AH*DIM];     // [m][d] : am_w2[d][m]
__device__ float g_PW2T [PH*DIM];     // [h][d] : pm_w2[d][h]
__device__ float g_cc   [AH];         // am_b1 + pm_b2 @ am_w1.T

// ---------------- kernel 0: model-weight derived tensors ----------------
__global__ void prep_weights(const float* __restrict__ pm_w2,
                             const float* __restrict__ am_w1,
                             const float* __restrict__ am_b1,
                             const float* __restrict__ pm_b2,
                             const float* __restrict__ am_w2) {
    __shared__ float sPW2[DIM*PH];               // pm_w2 [d][h]
    int t = threadIdx.x;                          // 256 threads
    for (int i = t; i < DIM*PH; i += 256) sPW2[i] = pm_w2[i];
    __syncthreads();

    int m = t;                                    // 0..255
    float a[DIM];
    const float4* ar = (const float4*)(am_w1 + m*DIM);
#pragma unroll
    for (int i = 0; i < DIM/4; i++) {
        float4 v = ar[i];
        a[4*i] = v.x; a[4*i+1] = v.y; a[4*i+2] = v.z; a[4*i+3] = v.w;
    }
    float cc = am_b1[m];
#pragma unroll 8
    for (int d = 0; d < DIM; d++) cc += pm_b2[d]*a[d];
    g_cc[m] = cc;

    for (int h = 0; h < PH; h++) {
        float s = 0.f;
#pragma unroll 8
        for (int d = 0; d < DIM; d++) s += a[d]*sPW2[d*PH + h];
        g_WcT[h*AH + m] = s;
    }
    for (int d = 0; d < DIM; d++) g_AMW2T[m*DIM + d] = am_w2[d*AH + m];
    if (t < PH) {
        int h = t;
        for (int d = 0; d < DIM; d++) g_PW2T[h*DIM + d] = sPW2[d*PH + h];
    }
}

// ---------------- kernel 1: per-point precompute ----------------
__global__ void prep_points(const float* __restrict__ x,
                            const float* __restrict__ pos,
                            const float* __restrict__ w_qkv,
                            const float* __restrict__ pm_w1,
                            const float* __restrict__ am_w1) {
    __shared__ float sx[DIM], sp[PIN], sq[DIM], sk[DIM];
    int pt = blockIdx.x;            // bt*128 + n
    int bt = pt >> 7, n = pt & 127;
    int t  = threadIdx.x;           // 128 threads

    if (t < DIM) sx[t] = x[(size_t)pt*DIM + t];
    if (t < PIN) {
        int c = t / 17, j = t % 17; // p[bt][n][c*17+j] = pos[b][tt][j][c][n]
        sp[t] = pos[(((size_t)bt*17 + j)*3 + c)*NPTS + n];
    }
    __syncthreads();

    // qkv rows
    for (int m = t; m < 3*DIM; m += 128) {
        const float4* wr = (const float4*)(w_qkv + m*DIM);
        float s = 0.f;
#pragma unroll
        for (int i = 0; i < DIM/4; i++) {
            float4 w  = wr[i];
            float4 xv = ((const float4*)sx)[i];
            s += w.x*xv.x + w.y*xv.y + w.z*xv.z + w.w*xv.w;
        }
        if      (m <   DIM) sq[m]        = s;
        else if (m < 2*DIM) sk[m-DIM]    = s;
        else g_V[(size_t)pt*DIM + (m-2*DIM)] = s;
    }
    // A = p @ pm_w1.T  (rows are 136B, scalar loads)
    if (t < DIM) {
        const float* wr = pm_w1 + t*PIN;
        float s = 0.f;
#pragma unroll
        for (int f = 0; f < PIN; f++) s += sp[f]*wr[f];
        g_A[(size_t)pt*DIM + t] = s;
    }
    __syncthreads();
    // U = q @ am_w1.T ; WK = k @ am_w1.T (share the weight-row load)
    for (int m = t; m < AH; m += 128) {
        const float4* wr = (const float4*)(am_w1 + m*DIM);
        float su = 0.f, sw = 0.f;
#pragma unroll
        for (int i = 0; i < DIM/4; i++) {
            float4 w  = wr[i];
            float4 qv = ((const float4*)sq)[i];
            float4 kv = ((const float4*)sk)[i];
            su += w.x*qv.x + w.y*qv.y + w.z*qv.z + w.w*qv.w;
            sw += w.x*kv.x + w.y*kv.y + w.z*kv.z + w.w*kv.w;
        }
        g_U [(size_t)pt*AH + m] = su;
        g_WK[(size_t)pt*AH + m] = sw;
    }
}

// ---------------- kernel 2: fused pairwise MLPs + softmax + aggregate ----------------
// Block = one (bt, i). 256 threads. j processed in 4 tiles of 32.
// smem float offsets
#define OFF_A    0            // 128*65  = 8320 (padded rows, conflict-free column access)
#define OFF_H1T  8320         // 64*36   = 2304 (H1 transposed [h][j'])
#define OFF_H2T  10624        // 256*36  = 9216 (H2 transposed [m][j'])
#define OFF_SIM  19840        // 128*64  = 8192
#define OFF_RPE  28032        // 128*64  = 8192
#define OFF_W2T  36224        // 256*64  = 16384 (am_w2 transposed)
#define OFF_UI   52608        // 256     (U_i + cc)
#define OFF_PB1  52864        // 64
#define OFF_PB2  52928        // 64
#define OFF_AB2  52992        // 64
#define OFF_RED  53056        // 768 (reductions)
#define SMEM_FLOATS 53824
#define SMEM_BYTES  (SMEM_FLOATS*4)

__global__ void __launch_bounds__(256, 1)
pt_layer_main(const float* __restrict__ pm_b1,
              const float* __restrict__ pm_b2,
              const float* __restrict__ am_b2,
              float* __restrict__ out) {
    extern __shared__ float sm[];
    float* sA   = sm + OFF_A;
    float* sH1T = sm + OFF_H1T;
    float* sH2T = sm + OFF_H2T;
    float* sSIM = sm + OFF_SIM;
    float* sRPE = sm + OFF_RPE;
    float* sW2T = sm + OFF_W2T;
    float* sUi  = sm + OFF_UI;
    float* sPB1 = sm + OFF_PB1;
    float* sPB2 = sm + OFF_PB2;
    float* sAB2 = sm + OFF_AB2;
    float* sRed = sm + OFF_RED;

    int t  = threadIdx.x;
    int bt = blockIdx.x >> 7;
    int i  = blockIdx.x & 127;
    size_t ptbase = (size_t)bt * NPTS;

    // ---- load phase ----
    for (int idx = t; idx < NPTS*DIM; idx += 256) {
        int j = idx >> 6, h = idx & 63;
        sA[j*65 + h] = g_A[ptbase*DIM + idx];
    }
    for (int idx = t; idx < (AH*DIM)/4; idx += 256)
        ((float4*)sW2T)[idx] = ((const float4*)g_AMW2T)[idx];
    sUi[t] = g_U[(ptbase + i)*AH + t] + g_cc[t];
    if (t < DIM) { sPB1[t] = pm_b1[t]; sPB2[t] = pm_b2[t]; sAB2[t] = am_b2[t]; }

    int tr = t >> 5;   // warp id 0..7  -> rows j' = tr*4..tr*4+3
    int tc = t & 31;   // lane 0..31

    for (int jt = 0; jt < 4; jt++) {
        int j0 = jt * 32;
        __syncthreads();   // protects sH1T/sH2T reuse + (jt==0) load phase

        // ---- H1[j'][h] = relu(a_i - a_j + b1), stored transposed ----
        {
            int jj = t >> 3;
            int hb = (t & 7) * 8;
#pragma unroll
            for (int q = 0; q < 8; q++) {
                int h = hb + q;
                float v = sA[i*65 + h] - sA[(j0+jj)*65 + h] + sPB1[h];
                sH1T[h*36 + jj] = fmaxf(v, 0.f);
            }
        }
        __syncthreads();

        // ---- GEMM1: Z1[32][256] = H1 @ Wc.T + (U_i - WK_j + cc), relu -> H2T ----
        float acc[4][8];
#pragma unroll
        for (int r = 0; r < 4; r++)
#pragma unroll
            for (int c = 0; c < 8; c++) acc[r][c] = 0.f;
#pragma unroll 8
        for (int k = 0; k < PH; k++) {
            float4 hv = *(const float4*)&sH1T[k*36 + tr*4];        // broadcast LDS
            const float4* wp = (const float4*)&g_WcT[k*AH + tc*8]; // coalesced L2
            float4 w0 = wp[0], w1 = wp[1];
            float hr[4] = {hv.x, hv.y, hv.z, hv.w};
            float wc[8] = {w0.x,w0.y,w0.z,w0.w,w1.x,w1.y,w1.z,w1.w};
#pragma unroll
            for (int r = 0; r < 4; r++)
#pragma unroll
                for (int c = 0; c < 8; c++) acc[r][c] = fmaf(hr[r], wc[c], acc[r][c]);
        }
        {
            float4 u0 = *(const float4*)&sUi[tc*8];
            float4 u1 = *(const float4*)&sUi[tc*8+4];
            float ui[8] = {u0.x,u0.y,u0.z,u0.w,u1.x,u1.y,u1.z,u1.w};
#pragma unroll
            for (int r = 0; r < 4; r++) {
                int jj = tr*4 + r;
                const float4* wkp = (const float4*)&g_WK[(ptbase + j0 + jj)*AH + tc*8];
                float4 k0 = wkp[0], k1 = wkp[1];
                float wk[8] = {k0.x,k0.y,k0.z,k0.w,k1.x,k1.y,k1.z,k1.w};
#pragma unroll
                for (int c = 0; c < 8; c++) {
                    float z = acc[r][c] + ui[c] - wk[c];
                    sH2T[(tc*8+c)*36 + jj] = fmaxf(z, 0.f);
                }
            }
        }
        __syncthreads();

        // ---- GEMM2: SIM[32][64] = H2 @ am_w2.T + b2 ----
        float a2[4][2] = {};
#pragma unroll 8
        for (int k = 0; k < AH; k++) {
            float4 hv = *(const float4*)&sH2T[k*36 + tr*4];
            float2 wv = *(const float2*)&sW2T[k*DIM + tc*2];
            float hr[4] = {hv.x,hv.y,hv.z,hv.w};
#pragma unroll
            for (int r = 0; r < 4; r++) {
                a2[r][0] = fmaf(hr[r], wv.x, a2[r][0]);
                a2[r][1] = fmaf(hr[r], wv.y, a2[r][1]);
            }
        }
#pragma unroll
        for (int r = 0; r < 4; r++) {
            int jj = tr*4 + r;
            float2 o;
            o.x = a2[r][0] + sAB2[tc*2];
            o.y = a2[r][1] + sAB2[tc*2+1];
            *(float2*)&sSIM[(j0+jj)*DIM + tc*2] = o;
        }

        // ---- RPE[32][64] = H1 @ pm_w2.T + pm_b2 ----
        float a3[4][2] = {};
#pragma unroll 8
        for (int k = 0; k < PH; k++) {
            float4 hv = *(const float4*)&sH1T[k*36 + tr*4];
            float2 wv = *(const float2*)&g_PW2T[k*DIM + tc*2];
            float hr[4] = {hv.x,hv.y,hv.z,hv.w};
#pragma unroll
            for (int r = 0; r < 4; r++) {
                a3[r][0] = fmaf(hr[r], wv.x, a3[r][0]);
                a3[r][1] = fmaf(hr[r], wv.y, a3[r][1]);
            }
        }
#pragma unroll
        for (int r = 0; r < 4; r++) {
            int jj = tr*4 + r;
            float2 o;
            o.x = a3[r][0] + sPB2[tc*2];
            o.y = a3[r][1] + sPB2[tc*2+1];
            *(float2*)&sRPE[(j0+jj)*DIM + tc*2] = o;
        }
    }
    __syncthreads();

    // ---- softmax over j (per column d) + aggregate ----
    {
        int d = t & 63;
        int g = t >> 6;          // 4 j-groups of 32
        int jlo = g * 32;
        float mx = -1e30f;
        for (int j = jlo; j < jlo+32; j++) mx = fmaxf(mx, sSIM[j*DIM + d]);
        sRed[g*64 + d] = mx;
        __syncthreads();
        mx = fmaxf(fmaxf(sRed[d], sRed[64+d]), fmaxf(sRed[128+d], sRed[192+d]));

        float se = 0.f, sa = 0.f;
        for (int j = jlo; j < jlo+32; j++) {
            float e  = __expf(sSIM[j*DIM + d] - mx);
            float vp = g_V[(ptbase + j)*DIM + d] + sRPE[j*DIM + d];
            se += e;
            sa  = fmaf(e, vp, sa);
        }
        __syncthreads();                 // all mx reads done before reuse
        sRed[g*64 + d]       = se;
        sRed[256 + g*64 + d] = sa;       // (sRed has 768 floats; uses [0..511])
        __syncthreads();
        if (g == 0) {
            float S  = sRed[d] + sRed[64+d] + sRed[128+d] + sRed[192+d];
            float Ag = sRed[256+d] + sRed[320+d] + sRed[384+d] + sRed[448+d];
            out[(ptbase + i)*DIM + d] = Ag / S;
        }
    }
}

// ---------------- launch ----------------
extern "C" void kernel_launch(void* const* d_in, const int* in_sizes, int n_in,
                              void* d_out, int out_size) {
    const float* x      = (const float*)d_in[0];
    const float* pos    = (const float*)d_in[1];
    const float* w_qkv  = (const float*)d_in[2];
    const float* pm_w1  = (const float*)d_in[3];
    const float* pm_b1  = (const float*)d_in[4];
    const float* pm_w2  = (const float*)d_in[5];
    const float* pm_b2  = (const float*)d_in[6];
    const float* am_w1  = (const float*)d_in[7];
    const float* am_b1  = (const float*)d_in[8];
    const float* am_w2  = (const float*)d_in[9];
    const float* am_b2  = (const float*)d_in[10];
    float* out = (float*)d_out;

    cudaFuncSetAttribute(pt_layer_main,
                         cudaFuncAttributeMaxDynamicSharedMemorySize, SMEM_BYTES);

    prep_weights<<<1, 256>>>(pm_w2, am_w1, am_b1, pm_b2, am_w2);
    prep_points <<<BT*NPTS, 128>>>(x, pos, w_qkv, pm_w1, am_w1);
    pt_layer_main<<<BT*NPTS, 256, SMEM_BYTES>>>(pm_b1, pm_b2, am_b2, out);
}